// round 14
// baseline (speedup 1.0000x reference)
#include <cuda_runtime.h>

#define KSEL 8
#define NB   16384
#define BQ   65536
#define FDIM 64
#define EPSF 1e-8f
#define INV_TEMP 200.0f   // 1 / (2*0.05*0.05)

#define GRES  16
#define NCELL (GRES * GRES * GRES)     // 4096
#define HCELL 0.0625f                  // 1/16
#define INVH  16.0f
#define TPB   128
#define QPB   64                        // queries per block (2 threads each)
#define MARGIN 1.0001f                 // covers fp rounding + (1+eps) weight bound

// ---- persistent scratch (device globals; no allocation) ----
__device__ int    g_hista[NCELL];
__device__ int    g_histq[NCELL];
__device__ int    g_starta[NCELL + 1];  // +1 sentinel: run end = starta[cell+1]
__device__ int    g_startq[NCELL + 1];  // consumed (destroyed) by scat_kernel
__device__ int    g_cnt2a[NCELL];
__device__ float4 g_spos[NB];          // anchors sorted by cell: {px,py,pz,inv_w2}
__device__ int    g_sorig[NB];         // sorted slot -> original anchor index
__device__ float4 g_qs[BQ];            // queries sorted by cell: {cx,cy,cz, bits(orig q)}

__device__ __forceinline__ int cellco(float v) {
    int c = (int)(v * INVH);
    return c > GRES - 1 ? GRES - 1 : (c < 0 ? 0 : c);
}
__device__ __forceinline__ int cellid(int x, int y, int z) {
    return (z * GRES + y) * GRES + x;
}

__global__ void zero_kernel() {
    int i = blockIdx.x * blockDim.x + threadIdx.x;
    if (i < NCELL) { g_hista[i] = 0; g_histq[i] = 0; g_cnt2a[i] = 0; }
}

// Fused histograms: thread i handles query i, and anchor i when i < NB.
__global__ void hist_kernel(const float* __restrict__ coords,
                            const float* __restrict__ pos) {
    int i = blockIdx.x * blockDim.x + threadIdx.x;
    if (i < BQ) {
        int c = cellid(cellco(coords[3 * i + 0]), cellco(coords[3 * i + 1]), cellco(coords[3 * i + 2]));
        atomicAdd(&g_histq[c], 1);
    }
    if (i < NB) {
        int c = cellid(cellco(pos[3 * i + 0]), cellco(pos[3 * i + 1]), cellco(pos[3 * i + 2]));
        atomicAdd(&g_hista[c], 1);
    }
}

// One block, 1024 threads; warp-shuffle scan of both 4096-entry histograms.
__global__ void scan_kernel() {
    __shared__ int wsum[32];
    const int t    = threadIdx.x;
    const int lane = t & 31;
    const int wid  = t >> 5;

#pragma unroll
    for (int pass = 0; pass < 2; ++pass) {
        const int* hist  = pass ? g_histq : g_hista;
        int*       start = pass ? g_startq : g_starta;
        const int  total = pass ? BQ : NB;

        int v0 = hist[4 * t + 0], v1 = hist[4 * t + 1];
        int v2 = hist[4 * t + 2], v3 = hist[4 * t + 3];
        int s = v0 + v1 + v2 + v3;

        int x = s;
#pragma unroll
        for (int off = 1; off < 32; off <<= 1) {
            int y = __shfl_up_sync(0xFFFFFFFFu, x, off);
            if (lane >= off) x += y;
        }
        if (lane == 31) wsum[wid] = x;
        __syncthreads();
        if (wid == 0) {
            int w = wsum[lane];
#pragma unroll
            for (int off = 1; off < 32; off <<= 1) {
                int y = __shfl_up_sync(0xFFFFFFFFu, w, off);
                if (lane >= off) w += y;
            }
            wsum[lane] = w;
        }
        __syncthreads();
        int base = (wid > 0 ? wsum[wid - 1] : 0) + (x - s);
        start[4 * t + 0] = base;
        start[4 * t + 1] = base + v0;
        start[4 * t + 2] = base + v0 + v1;
        start[4 * t + 3] = base + v0 + v1 + v2;
        if (t == 1023) start[NCELL] = total;
        __syncthreads();
    }
}

// Fused scatter: thread i scatters query i (consuming g_startq), and anchor i.
__global__ void scat_kernel(const float* __restrict__ coords,
                            const float* __restrict__ pos,
                            const float* __restrict__ w) {
    int i = blockIdx.x * blockDim.x + threadIdx.x;
    if (i < BQ) {
        float cx = coords[3 * i + 0], cy = coords[3 * i + 1], cz = coords[3 * i + 2];
        int c = cellid(cellco(cx), cellco(cy), cellco(cz));
        int slot = atomicAdd(&g_startq[c], 1);    // startq is dead after this pass
        g_qs[slot] = make_float4(cx, cy, cz, __int_as_float(i));
    }
    if (i < NB) {
        float px = pos[3 * i + 0], py = pos[3 * i + 1], pz = pos[3 * i + 2];
        int c = cellid(cellco(px), cellco(py), cellco(pz));
        int slot = g_starta[c] + atomicAdd(&g_cnt2a[c], 1);
        float wi = w[i];
        g_spos[slot]  = make_float4(px, py, pz, 1.0f / (wi * wi + EPSF));
        g_sorig[slot] = i;
    }
}

__device__ __forceinline__ void ins8(float sq, int jj, float d[KSEL], int id[KSEL], float& worst) {
    if (sq < worst) {
        d[KSEL - 1]  = sq;
        id[KSEL - 1] = jj;
#pragma unroll
        for (int k = KSEL - 1; k > 0; --k) {
            if (d[k] < d[k - 1]) {
                float td = d[k]; d[k] = d[k - 1]; d[k - 1] = td;
                int   ti = id[k]; id[k] = id[k - 1]; id[k - 1] = ti;
            }
        }
        worst = d[KSEL - 1];
    }
}

// Scan a contiguous slab of sorted anchors [s, e).
__device__ __forceinline__ void scan_run(int s, int e,
                                         float cx, float cy, float cz,
                                         float d[KSEL], int id[KSEL], float& worst) {
#pragma unroll 2
    for (int j = s; j < e; ++j) {
        float4 p = g_spos[j];
        float ddx = cx - p.x, ddy = cy - p.y, ddz = cz - p.z;
        float sq = fmaf(ddz, ddz, fmaf(ddy, ddy, ddx * ddx)) * p.w;
        ins8(sq, j, d, id, worst);
    }
}

__global__ __launch_bounds__(TPB) void knn_grid_kernel(
    const float* __restrict__ features,
    float* __restrict__ out)
{
    __shared__ struct {
        float md[QPB][KSEL];      // sub1's top-8 distances
        int   mi[QPB][KSEL];      // sub1's top-8 indices (sorted-slot)
        float w[QPB][KSEL];       // final softmax weights
        int   idx[QPB][KSEL];     // final original anchor indices
        int   oq[QPB];
    } ep;

    const int tid = threadIdx.x;
    const int qt  = tid & (QPB - 1);
    const int sub = tid >> 6;               // 0: even dz rows, 1: odd dz rows
    const int gid = blockIdx.x * QPB + qt;

    const float4 qr = g_qs[gid];
    const float cx = qr.x, cy = qr.y, cz = qr.z;
    const int   oq = __float_as_int(qr.w);

    const int qcx = cellco(cx), qcy = cellco(cy), qcz = cellco(cz);

    float d[KSEL];
    int   id[KSEL];
#pragma unroll
    for (int k = 0; k < KSEL; ++k) { d[k] = 3.4e38f; id[k] = 0; }
    float worst = 3.4e38f;

    // ---- Seed: this sub's parity rows of the 3x3x3 neighborhood ----
    const int sxl = qcx > 0 ? qcx - 1 : 0;
    const int sxh = qcx < GRES - 1 ? qcx + 1 : GRES - 1;
#pragma unroll
    for (int dz = -1; dz <= 1; ++dz) {
        if ((dz & 1) != sub) continue;
        int z = qcz + dz;
        if (z < 0 || z > GRES - 1) continue;
#pragma unroll
        for (int dy = -1; dy <= 1; ++dy) {
            int y = qcy + dy;
            if (y < 0 || y > GRES - 1) continue;
            int s = g_starta[cellid(sxl, y, z)];
            int e = g_starta[cellid(sxh, y, z) + 1];
            scan_run(s, e, cx, cy, cz, d, id, worst);
        }
    }

    // ---- Main: this sub's parity dz rows, analytic x-ranges ----
    float bound = worst * MARGIN;
    int rlim = (int)(sqrtf(bound) * INVH) + 1;
    if (rlim > GRES) rlim = GRES;

    int dz0 = -rlim;
    if ((dz0 & 1) != sub) dz0++;

    for (int dz = dz0; dz <= rlim; dz += 2) {
        int z = qcz + dz;
        if (z < 0 || z > GRES - 1) continue;
        float lz = (float)z * HCELL;
        float ez = fmaxf(fmaxf(lz - cz, cz - (lz + HCELL)), 0.0f);
        float ez2 = ez * ez;
        bound = worst * MARGIN;
        if (ez2 >= bound) continue;

        for (int dy = -rlim; dy <= rlim; ++dy) {
            int y = qcy + dy;
            if (y < 0 || y > GRES - 1) continue;
            float ly = (float)y * HCELL;
            float eyv = fmaxf(fmaxf(ly - cy, cy - (ly + HCELL)), 0.0f);
            float row2 = fmaf(eyv, eyv, ez2);
            bound = worst * MARGIN;
            if (row2 >= bound) continue;

            // exact passing x-range for this row
            float xr = sqrtf(bound - row2);
            int xlo = (int)floorf((cx - xr) * INVH);
            int xhi = (int)floorf((cx + xr) * INVH);
            if (xlo < 0) xlo = 0;
            if (xhi > GRES - 1) xhi = GRES - 1;

            if (dz >= -1 && dz <= 1 && dy >= -1 && dy <= 1) {
                // exclude the seeded sub-range [sxl, sxh]
                if (xlo < sxl) {
                    int s = g_starta[cellid(xlo, y, z)];
                    int e = g_starta[cellid(sxl - 1, y, z) + 1];
                    scan_run(s, e, cx, cy, cz, d, id, worst);
                }
                if (xhi > sxh) {
                    int s = g_starta[cellid(sxh + 1, y, z)];
                    int e = g_starta[cellid(xhi, y, z) + 1];
                    scan_run(s, e, cx, cy, cz, d, id, worst);
                }
            } else {
                int s = g_starta[cellid(xlo, y, z)];
                int e = g_starta[cellid(xhi, y, z) + 1];
                scan_run(s, e, cx, cy, cz, d, id, worst);
            }
        }
    }

    // ---- Merge the two subs' top-8, softmax (sub 0 does the work) ----
    if (sub == 1) {
#pragma unroll
        for (int k = 0; k < KSEL; ++k) {
            ep.md[qt][k] = d[k];
            ep.mi[qt][k] = id[k];
        }
    }
    __syncthreads();

    if (sub == 0) {
#pragma unroll
        for (int k = 0; k < KSEL; ++k)
            ins8(ep.md[qt][k], ep.mi[qt][k], d, id, worst);

        float m0 = d[0], wsum = 0.0f, wk[KSEL];
#pragma unroll
        for (int k = 0; k < KSEL; ++k) { wk[k] = __expf((m0 - d[k]) * INV_TEMP); wsum += wk[k]; }
        float inv = 1.0f / wsum;
#pragma unroll
        for (int k = 0; k < KSEL; ++k) {
            ep.w[qt][k]   = wk[k] * inv;
            ep.idx[qt][k] = g_sorig[id[k]];
        }
        ep.oq[qt] = oq;
    }
    __syncthreads();

    // Cooperative gather: 4 warps x 16 queries; lane L accumulates features
    // [2L, 2L+1] (float2); each output row is a contiguous 256B write.
    const int lane = tid & 31;
    const int warp = tid >> 5;
    for (int qq = 0; qq < QPB / 4; ++qq) {
        const int tq = warp * (QPB / 4) + qq;
        float2 acc = make_float2(0.0f, 0.0f);
#pragma unroll
        for (int k = 0; k < KSEL; ++k) {
            const int   ii = ep.idx[tq][k];
            const float ww = ep.w[tq][k];
            float2 f = ((const float2*)(features + (size_t)ii * FDIM))[lane];
            acc.x = fmaf(ww, f.x, acc.x);
            acc.y = fmaf(ww, f.y, acc.y);
        }
        ((float2*)out)[(size_t)ep.oq[tq] * 32 + lane] = acc;
    }
}

extern "C" void kernel_launch(void* const* d_in, const int* in_sizes, int n_in,
                              void* d_out, int out_size) {
    const float* coords    = (const float*)d_in[0];
    const float* positions = (const float*)d_in[1];
    const float* weights   = (const float*)d_in[2];
    const float* features  = (const float*)d_in[3];
    float* out = (float*)d_out;

    zero_kernel<<<NCELL / 256, 256>>>();
    hist_kernel<<<BQ / 256, 256>>>(coords, positions);
    scan_kernel<<<1, 1024>>>();
    scat_kernel<<<BQ / 256, 256>>>(coords, positions, weights);
    knn_grid_kernel<<<BQ / QPB, TPB>>>(features, out);
}

// round 15
// speedup vs baseline: 2.2066x; 2.2066x over previous
#include <cuda_runtime.h>

#define KSEL 8
#define NB   16384
#define BQ   65536
#define FDIM 64
#define EPSF 1e-8f
#define INV_TEMP 200.0f   // 1 / (2*0.05*0.05)

#define GRES  16
#define NCELL (GRES * GRES * GRES)     // 4096
#define HCELL 0.0625f                  // 1/16
#define INVH  16.0f
#define TPB   64
#define MARGIN 1.0001f                 // covers fp rounding + (1+eps) weight bound

// ---- persistent scratch (device globals; no allocation) ----
// Zero-initialized at module load; re-zeroed by knn_grid_kernel for the next
// graph replay (stream order guarantees no overlap with the next hist pass).
__device__ int    g_hista[NCELL];
__device__ int    g_histq[NCELL];
__device__ int    g_starta[NCELL + 1];  // +1 sentinel: run end = starta[cell+1]
__device__ int    g_startq[NCELL + 1];  // consumed (destroyed) by scat_kernel
__device__ int    g_cnt2a[NCELL];
__device__ float4 g_spos[NB];          // anchors sorted by cell: {px,py,pz,inv_w2}
__device__ int    g_sorig[NB];         // sorted slot -> original anchor index
__device__ float4 g_qs[BQ];            // queries sorted by cell: {cx,cy,cz, bits(orig q)}

__device__ __forceinline__ int cellco(float v) {
    int c = (int)(v * INVH);
    return c > GRES - 1 ? GRES - 1 : (c < 0 ? 0 : c);
}
__device__ __forceinline__ int cellid(int x, int y, int z) {
    return (z * GRES + y) * GRES + x;
}

// Fused histograms: thread i handles query i, and anchor i when i < NB.
__global__ void hist_kernel(const float* __restrict__ coords,
                            const float* __restrict__ pos) {
    int i = blockIdx.x * blockDim.x + threadIdx.x;
    if (i < BQ) {
        int c = cellid(cellco(coords[3 * i + 0]), cellco(coords[3 * i + 1]), cellco(coords[3 * i + 2]));
        atomicAdd(&g_histq[c], 1);
    }
    if (i < NB) {
        int c = cellid(cellco(pos[3 * i + 0]), cellco(pos[3 * i + 1]), cellco(pos[3 * i + 2]));
        atomicAdd(&g_hista[c], 1);
    }
}

// One block, 1024 threads; warp-shuffle scan of both 4096-entry histograms.
__global__ void scan_kernel() {
    __shared__ int wsum[32];
    const int t    = threadIdx.x;
    const int lane = t & 31;
    const int wid  = t >> 5;

#pragma unroll
    for (int pass = 0; pass < 2; ++pass) {
        const int* hist  = pass ? g_histq : g_hista;
        int*       start = pass ? g_startq : g_starta;
        const int  total = pass ? BQ : NB;

        int v0 = hist[4 * t + 0], v1 = hist[4 * t + 1];
        int v2 = hist[4 * t + 2], v3 = hist[4 * t + 3];
        int s = v0 + v1 + v2 + v3;

        int x = s;
#pragma unroll
        for (int off = 1; off < 32; off <<= 1) {
            int y = __shfl_up_sync(0xFFFFFFFFu, x, off);
            if (lane >= off) x += y;
        }
        if (lane == 31) wsum[wid] = x;
        __syncthreads();
        if (wid == 0) {
            int w = wsum[lane];
#pragma unroll
            for (int off = 1; off < 32; off <<= 1) {
                int y = __shfl_up_sync(0xFFFFFFFFu, w, off);
                if (lane >= off) w += y;
            }
            wsum[lane] = w;
        }
        __syncthreads();
        int base = (wid > 0 ? wsum[wid - 1] : 0) + (x - s);
        start[4 * t + 0] = base;
        start[4 * t + 1] = base + v0;
        start[4 * t + 2] = base + v0 + v1;
        start[4 * t + 3] = base + v0 + v1 + v2;
        if (t == 1023) start[NCELL] = total;
        __syncthreads();
    }
}

// Fused scatter: thread i scatters query i (consuming g_startq), and anchor i.
__global__ void scat_kernel(const float* __restrict__ coords,
                            const float* __restrict__ pos,
                            const float* __restrict__ w) {
    int i = blockIdx.x * blockDim.x + threadIdx.x;
    if (i < BQ) {
        float cx = coords[3 * i + 0], cy = coords[3 * i + 1], cz = coords[3 * i + 2];
        int c = cellid(cellco(cx), cellco(cy), cellco(cz));
        int slot = atomicAdd(&g_startq[c], 1);    // startq is dead after this pass
        g_qs[slot] = make_float4(cx, cy, cz, __int_as_float(i));
    }
    if (i < NB) {
        float px = pos[3 * i + 0], py = pos[3 * i + 1], pz = pos[3 * i + 2];
        int c = cellid(cellco(px), cellco(py), cellco(pz));
        int slot = g_starta[c] + atomicAdd(&g_cnt2a[c], 1);
        float wi = w[i];
        g_spos[slot]  = make_float4(px, py, pz, 1.0f / (wi * wi + EPSF));
        g_sorig[slot] = i;
    }
}

__device__ __forceinline__ void ins8(float sq, int jj, float d[KSEL], int id[KSEL], float& worst) {
    if (sq < worst) {
        d[KSEL - 1]  = sq;
        id[KSEL - 1] = jj;
#pragma unroll
        for (int k = KSEL - 1; k > 0; --k) {
            if (d[k] < d[k - 1]) {
                float td = d[k]; d[k] = d[k - 1]; d[k - 1] = td;
                int   ti = id[k]; id[k] = id[k - 1]; id[k - 1] = ti;
            }
        }
        worst = d[KSEL - 1];
    }
}

// Scan a contiguous slab of sorted anchors [s, e).
// 4-wide: 4 independent LDG.128 in flight, one min-tree, one rare branch per 4.
__device__ __forceinline__ void scan_run(int s, int e,
                                         float cx, float cy, float cz,
                                         float d[KSEL], int id[KSEL], float& worst) {
    int j = s;
    for (; j + 4 <= e; j += 4) {
        float4 p0 = g_spos[j + 0];
        float4 p1 = g_spos[j + 1];
        float4 p2 = g_spos[j + 2];
        float4 p3 = g_spos[j + 3];

        float x0 = cx - p0.x, y0 = cy - p0.y, z0 = cz - p0.z;
        float x1 = cx - p1.x, y1 = cy - p1.y, z1 = cz - p1.z;
        float x2 = cx - p2.x, y2 = cy - p2.y, z2 = cz - p2.z;
        float x3 = cx - p3.x, y3 = cy - p3.y, z3 = cz - p3.z;

        float s0 = fmaf(z0, z0, fmaf(y0, y0, x0 * x0)) * p0.w;
        float s1 = fmaf(z1, z1, fmaf(y1, y1, x1 * x1)) * p1.w;
        float s2 = fmaf(z2, z2, fmaf(y2, y2, x2 * x2)) * p2.w;
        float s3 = fmaf(z3, z3, fmaf(y3, y3, x3 * x3)) * p3.w;

        float m = fminf(fminf(s0, s1), fminf(s2, s3));
        if (m < worst) {
            ins8(s0, j + 0, d, id, worst);
            ins8(s1, j + 1, d, id, worst);
            ins8(s2, j + 2, d, id, worst);
            ins8(s3, j + 3, d, id, worst);
        }
    }
    for (; j < e; ++j) {
        float4 p = g_spos[j];
        float ddx = cx - p.x, ddy = cy - p.y, ddz = cz - p.z;
        float sq = fmaf(ddz, ddz, fmaf(ddy, ddy, ddx * ddx)) * p.w;
        ins8(sq, j, d, id, worst);
    }
}

__global__ __launch_bounds__(TPB) void knn_grid_kernel(
    const float* __restrict__ features,
    float* __restrict__ out)
{
    __shared__ struct {
        float w[TPB][KSEL];
        int   idx[TPB][KSEL];
        int   oq[TPB];
    } ep;

    const int tid = threadIdx.x;
    const int gid = blockIdx.x * TPB + tid;

    // Re-zero hist/count arrays for the NEXT graph replay (nobody reads them
    // again within this replay; stream order protects the next one).
    if (gid < NCELL) { g_hista[gid] = 0; g_histq[gid] = 0; g_cnt2a[gid] = 0; }

    const float4 qr = g_qs[gid];
    const float cx = qr.x, cy = qr.y, cz = qr.z;
    const int   oq = __float_as_int(qr.w);

    const int qcx = cellco(cx), qcy = cellco(cy), qcz = cellco(cz);

    float d[KSEL];
    int   id[KSEL];
#pragma unroll
    for (int k = 0; k < KSEL; ++k) { d[k] = 3.4e38f; id[k] = 0; }
    float worst = 3.4e38f;

    // ---- Seed: 3x3x3 neighborhood, 9 contiguous x-runs, no pruning ----
    const int sxl = qcx > 0 ? qcx - 1 : 0;
    const int sxh = qcx < GRES - 1 ? qcx + 1 : GRES - 1;
#pragma unroll
    for (int dz = -1; dz <= 1; ++dz) {
        int z = qcz + dz;
        if (z < 0 || z > GRES - 1) continue;
#pragma unroll
        for (int dy = -1; dy <= 1; ++dy) {
            int y = qcy + dy;
            if (y < 0 || y > GRES - 1) continue;
            int s = g_starta[cellid(sxl, y, z)];
            int e = g_starta[cellid(sxh, y, z) + 1];
            scan_run(s, e, cx, cy, cz, d, id, worst);
        }
    }

    // ---- Main: row-wise expansion with analytic x-ranges ----
    float bound = worst * MARGIN;
    int rlim = (int)(sqrtf(bound) * INVH) + 1;
    if (rlim > GRES) rlim = GRES;

    for (int dz = -rlim; dz <= rlim; ++dz) {
        int z = qcz + dz;
        if (z < 0 || z > GRES - 1) continue;
        float lz = (float)z * HCELL;
        float ez = fmaxf(fmaxf(lz - cz, cz - (lz + HCELL)), 0.0f);
        float ez2 = ez * ez;
        bound = worst * MARGIN;
        if (ez2 >= bound) continue;

        for (int dy = -rlim; dy <= rlim; ++dy) {
            int y = qcy + dy;
            if (y < 0 || y > GRES - 1) continue;
            float ly = (float)y * HCELL;
            float eyv = fmaxf(fmaxf(ly - cy, cy - (ly + HCELL)), 0.0f);
            float row2 = fmaf(eyv, eyv, ez2);
            bound = worst * MARGIN;
            if (row2 >= bound) continue;

            // exact passing x-range for this row
            float xr = sqrtf(bound - row2);
            int xlo = (int)floorf((cx - xr) * INVH);
            int xhi = (int)floorf((cx + xr) * INVH);
            if (xlo < 0) xlo = 0;
            if (xhi > GRES - 1) xhi = GRES - 1;

            if (dz >= -1 && dz <= 1 && dy >= -1 && dy <= 1) {
                // exclude the seeded sub-range [sxl, sxh]
                if (xlo < sxl) {
                    int s = g_starta[cellid(xlo, y, z)];
                    int e = g_starta[cellid(sxl - 1, y, z) + 1];
                    scan_run(s, e, cx, cy, cz, d, id, worst);
                }
                if (xhi > sxh) {
                    int s = g_starta[cellid(sxh + 1, y, z)];
                    int e = g_starta[cellid(xhi, y, z) + 1];
                    scan_run(s, e, cx, cy, cz, d, id, worst);
                }
            } else {
                int s = g_starta[cellid(xlo, y, z)];
                int e = g_starta[cellid(xhi, y, z) + 1];
                scan_run(s, e, cx, cy, cz, d, id, worst);
            }
        }
    }

    // Softmax over the 8 selected (logit = -sq * INV_TEMP), max-subtracted.
    {
        float m0 = d[0], wsum = 0.0f, wk[KSEL];
#pragma unroll
        for (int k = 0; k < KSEL; ++k) { wk[k] = __expf((m0 - d[k]) * INV_TEMP); wsum += wk[k]; }
        float inv = 1.0f / wsum;
#pragma unroll
        for (int k = 0; k < KSEL; ++k) {
            ep.w[tid][k]   = wk[k] * inv;
            ep.idx[tid][k] = g_sorig[id[k]];
        }
        ep.oq[tid] = oq;
    }
    __syncthreads();

    // Cooperative gather: 2 warps x 32 queries; lane L accumulates features
    // [2L, 2L+1] (float2); each output row is a contiguous 256B write.
    const int lane = tid & 31;
    const int warp = tid >> 5;
    for (int qq = 0; qq < 32; ++qq) {
        const int tq = warp * 32 + qq;
        float2 acc = make_float2(0.0f, 0.0f);
#pragma unroll
        for (int k = 0; k < KSEL; ++k) {
            const int   ii = ep.idx[tq][k];
            const float ww = ep.w[tq][k];
            float2 f = ((const float2*)(features + (size_t)ii * FDIM))[lane];
            acc.x = fmaf(ww, f.x, acc.x);
            acc.y = fmaf(ww, f.y, acc.y);
        }
        ((float2*)out)[(size_t)ep.oq[tq] * 32 + lane] = acc;
    }
}

extern "C" void kernel_launch(void* const* d_in, const int* in_sizes, int n_in,
                              void* d_out, int out_size) {
    const float* coords    = (const float*)d_in[0];
    const float* positions = (const float*)d_in[1];
    const float* weights   = (const float*)d_in[2];
    const float* features  = (const float*)d_in[3];
    float* out = (float*)d_out;

    hist_kernel<<<BQ / 256, 256>>>(coords, positions);
    scan_kernel<<<1, 1024>>>();
    scat_kernel<<<BQ / 256, 256>>>(coords, positions, weights);
    knn_grid_kernel<<<BQ / TPB, TPB>>>(features, out);
}

// round 16
// speedup vs baseline: 2.7196x; 1.2325x over previous
#include <cuda_runtime.h>

#define KSEL 8
#define NB   16384
#define BQ   65536
#define FDIM 64
#define EPSF 1e-8f
#define INV_TEMP 200.0f   // 1 / (2*0.05*0.05)

#define GRES  16
#define NCELL (GRES * GRES * GRES)     // 4096
#define HCELL 0.0625f                  // 1/16
#define INVH  16.0f
#define TPB   64
#define MARGIN 1.0001f                 // covers fp rounding + (1+eps) weight bound

// ---- persistent scratch (device globals; no allocation) ----
// Zero-initialized at module load; re-zeroed by knn_grid_kernel for the next
// graph replay (stream order guarantees no overlap with the next hist pass).
__device__ int    g_hista[NCELL];
__device__ int    g_histq[NCELL];
__device__ int    g_starta[NCELL + 1];  // +1 sentinel: run end = starta[cell+1]
__device__ int    g_startq[NCELL + 1];  // consumed (destroyed) by scat_kernel
__device__ int    g_cnt2a[NCELL];
__device__ float4 g_spos[NB];          // anchors sorted by cell: {px,py,pz,inv_w2}
__device__ int    g_sorig[NB];         // sorted slot -> original anchor index
__device__ float4 g_qs[BQ];            // queries sorted by cell: {cx,cy,cz, bits(orig q)}

__device__ __forceinline__ int cellco(float v) {
    int c = (int)(v * INVH);
    return c > GRES - 1 ? GRES - 1 : (c < 0 ? 0 : c);
}
__device__ __forceinline__ int cellid(int x, int y, int z) {
    return (z * GRES + y) * GRES + x;
}

// Fused histograms: thread i handles query i, and anchor i when i < NB.
__global__ void hist_kernel(const float* __restrict__ coords,
                            const float* __restrict__ pos) {
    int i = blockIdx.x * blockDim.x + threadIdx.x;
    if (i < BQ) {
        int c = cellid(cellco(coords[3 * i + 0]), cellco(coords[3 * i + 1]), cellco(coords[3 * i + 2]));
        atomicAdd(&g_histq[c], 1);
    }
    if (i < NB) {
        int c = cellid(cellco(pos[3 * i + 0]), cellco(pos[3 * i + 1]), cellco(pos[3 * i + 2]));
        atomicAdd(&g_hista[c], 1);
    }
}

// One block, 1024 threads; warp-shuffle scan of both 4096-entry histograms.
__global__ void scan_kernel() {
    __shared__ int wsum[32];
    const int t    = threadIdx.x;
    const int lane = t & 31;
    const int wid  = t >> 5;

#pragma unroll
    for (int pass = 0; pass < 2; ++pass) {
        const int* hist  = pass ? g_histq : g_hista;
        int*       start = pass ? g_startq : g_starta;
        const int  total = pass ? BQ : NB;

        int v0 = hist[4 * t + 0], v1 = hist[4 * t + 1];
        int v2 = hist[4 * t + 2], v3 = hist[4 * t + 3];
        int s = v0 + v1 + v2 + v3;

        int x = s;
#pragma unroll
        for (int off = 1; off < 32; off <<= 1) {
            int y = __shfl_up_sync(0xFFFFFFFFu, x, off);
            if (lane >= off) x += y;
        }
        if (lane == 31) wsum[wid] = x;
        __syncthreads();
        if (wid == 0) {
            int w = wsum[lane];
#pragma unroll
            for (int off = 1; off < 32; off <<= 1) {
                int y = __shfl_up_sync(0xFFFFFFFFu, w, off);
                if (lane >= off) w += y;
            }
            wsum[lane] = w;
        }
        __syncthreads();
        int base = (wid > 0 ? wsum[wid - 1] : 0) + (x - s);
        start[4 * t + 0] = base;
        start[4 * t + 1] = base + v0;
        start[4 * t + 2] = base + v0 + v1;
        start[4 * t + 3] = base + v0 + v1 + v2;
        if (t == 1023) start[NCELL] = total;
        __syncthreads();
    }
}

// Fused scatter: thread i scatters query i (consuming g_startq), and anchor i.
__global__ void scat_kernel(const float* __restrict__ coords,
                            const float* __restrict__ pos,
                            const float* __restrict__ w) {
    int i = blockIdx.x * blockDim.x + threadIdx.x;
    if (i < BQ) {
        float cx = coords[3 * i + 0], cy = coords[3 * i + 1], cz = coords[3 * i + 2];
        int c = cellid(cellco(cx), cellco(cy), cellco(cz));
        int slot = atomicAdd(&g_startq[c], 1);    // startq is dead after this pass
        g_qs[slot] = make_float4(cx, cy, cz, __int_as_float(i));
    }
    if (i < NB) {
        float px = pos[3 * i + 0], py = pos[3 * i + 1], pz = pos[3 * i + 2];
        int c = cellid(cellco(px), cellco(py), cellco(pz));
        int slot = g_starta[c] + atomicAdd(&g_cnt2a[c], 1);
        float wi = w[i];
        g_spos[slot]  = make_float4(px, py, pz, 1.0f / (wi * wi + EPSF));
        g_sorig[slot] = i;
    }
}

__device__ __forceinline__ void ins8(float sq, int jj, float d[KSEL], int id[KSEL], float& worst) {
    if (sq < worst) {
        d[KSEL - 1]  = sq;
        id[KSEL - 1] = jj;
#pragma unroll
        for (int k = KSEL - 1; k > 0; --k) {
            if (d[k] < d[k - 1]) {
                float td = d[k]; d[k] = d[k - 1]; d[k - 1] = td;
                int   ti = id[k]; id[k] = id[k - 1]; id[k - 1] = ti;
            }
        }
        worst = d[KSEL - 1];
    }
}

// Scan a contiguous slab of sorted anchors [s, e).
// 1-wide with ins8's own early-out: minimal executed slots (R13-proven; the
// 4-wide variant tripled issued instructions and regressed 40%).
__device__ __forceinline__ void scan_run(int s, int e,
                                         float cx, float cy, float cz,
                                         float d[KSEL], int id[KSEL], float& worst) {
#pragma unroll 2
    for (int j = s; j < e; ++j) {
        float4 p = g_spos[j];
        float ddx = cx - p.x, ddy = cy - p.y, ddz = cz - p.z;
        float sq = fmaf(ddz, ddz, fmaf(ddy, ddy, ddx * ddx)) * p.w;
        ins8(sq, j, d, id, worst);
    }
}

__global__ __launch_bounds__(TPB) void knn_grid_kernel(
    const float* __restrict__ features,
    float* __restrict__ out)
{
    __shared__ struct {
        float w[TPB][KSEL];
        int   idx[TPB][KSEL];
        int   oq[TPB];
    } ep;

    const int tid = threadIdx.x;
    const int gid = blockIdx.x * TPB + tid;

    // Re-zero hist/count arrays for the NEXT graph replay (nobody reads them
    // again within this replay; stream order protects the next one).
    if (gid < NCELL) { g_hista[gid] = 0; g_histq[gid] = 0; g_cnt2a[gid] = 0; }

    const float4 qr = g_qs[gid];
    const float cx = qr.x, cy = qr.y, cz = qr.z;
    const int   oq = __float_as_int(qr.w);

    const int qcx = cellco(cx), qcy = cellco(cy), qcz = cellco(cz);

    float d[KSEL];
    int   id[KSEL];
#pragma unroll
    for (int k = 0; k < KSEL; ++k) { d[k] = 3.4e38f; id[k] = 0; }
    float worst = 3.4e38f;

    // ---- Seed: 3x3x3 neighborhood, 9 contiguous x-runs, no pruning ----
    const int sxl = qcx > 0 ? qcx - 1 : 0;
    const int sxh = qcx < GRES - 1 ? qcx + 1 : GRES - 1;
#pragma unroll
    for (int dz = -1; dz <= 1; ++dz) {
        int z = qcz + dz;
        if (z < 0 || z > GRES - 1) continue;
#pragma unroll
        for (int dy = -1; dy <= 1; ++dy) {
            int y = qcy + dy;
            if (y < 0 || y > GRES - 1) continue;
            int s = g_starta[cellid(sxl, y, z)];
            int e = g_starta[cellid(sxh, y, z) + 1];
            scan_run(s, e, cx, cy, cz, d, id, worst);
        }
    }

    // ---- Main: row-wise expansion with analytic x-ranges ----
    float bound = worst * MARGIN;
    int rlim = (int)(sqrtf(bound) * INVH) + 1;
    if (rlim > GRES) rlim = GRES;

    for (int dz = -rlim; dz <= rlim; ++dz) {
        int z = qcz + dz;
        if (z < 0 || z > GRES - 1) continue;
        float lz = (float)z * HCELL;
        float ez = fmaxf(fmaxf(lz - cz, cz - (lz + HCELL)), 0.0f);
        float ez2 = ez * ez;
        bound = worst * MARGIN;
        if (ez2 >= bound) continue;

        for (int dy = -rlim; dy <= rlim; ++dy) {
            int y = qcy + dy;
            if (y < 0 || y > GRES - 1) continue;
            float ly = (float)y * HCELL;
            float eyv = fmaxf(fmaxf(ly - cy, cy - (ly + HCELL)), 0.0f);
            float row2 = fmaf(eyv, eyv, ez2);
            bound = worst * MARGIN;
            if (row2 >= bound) continue;

            // exact passing x-range for this row
            float xr = sqrtf(bound - row2);
            int xlo = (int)floorf((cx - xr) * INVH);
            int xhi = (int)floorf((cx + xr) * INVH);
            if (xlo < 0) xlo = 0;
            if (xhi > GRES - 1) xhi = GRES - 1;

            if (dz >= -1 && dz <= 1 && dy >= -1 && dy <= 1) {
                // exclude the seeded sub-range [sxl, sxh]
                if (xlo < sxl) {
                    int s = g_starta[cellid(xlo, y, z)];
                    int e = g_starta[cellid(sxl - 1, y, z) + 1];
                    scan_run(s, e, cx, cy, cz, d, id, worst);
                }
                if (xhi > sxh) {
                    int s = g_starta[cellid(sxh + 1, y, z)];
                    int e = g_starta[cellid(xhi, y, z) + 1];
                    scan_run(s, e, cx, cy, cz, d, id, worst);
                }
            } else {
                int s = g_starta[cellid(xlo, y, z)];
                int e = g_starta[cellid(xhi, y, z) + 1];
                scan_run(s, e, cx, cy, cz, d, id, worst);
            }
        }
    }

    // Softmax over the 8 selected (logit = -sq * INV_TEMP), max-subtracted.
    {
        float m0 = d[0], wsum = 0.0f, wk[KSEL];
#pragma unroll
        for (int k = 0; k < KSEL; ++k) { wk[k] = __expf((m0 - d[k]) * INV_TEMP); wsum += wk[k]; }
        float inv = 1.0f / wsum;
#pragma unroll
        for (int k = 0; k < KSEL; ++k) {
            ep.w[tid][k]   = wk[k] * inv;
            ep.idx[tid][k] = g_sorig[id[k]];
        }
        ep.oq[tid] = oq;
    }
    __syncthreads();

    // Cooperative gather: 2 warps x 32 queries; lane L accumulates features
    // [2L, 2L+1] (float2); each output row is a contiguous 256B write.
    const int lane = tid & 31;
    const int warp = tid >> 5;
    for (int qq = 0; qq < 32; ++qq) {
        const int tq = warp * 32 + qq;
        float2 acc = make_float2(0.0f, 0.0f);
#pragma unroll
        for (int k = 0; k < KSEL; ++k) {
            const int   ii = ep.idx[tq][k];
            const float ww = ep.w[tq][k];
            float2 f = ((const float2*)(features + (size_t)ii * FDIM))[lane];
            acc.x = fmaf(ww, f.x, acc.x);
            acc.y = fmaf(ww, f.y, acc.y);
        }
        ((float2*)out)[(size_t)ep.oq[tq] * 32 + lane] = acc;
    }
}

extern "C" void kernel_launch(void* const* d_in, const int* in_sizes, int n_in,
                              void* d_out, int out_size) {
    const float* coords    = (const float*)d_in[0];
    const float* positions = (const float*)d_in[1];
    const float* weights   = (const float*)d_in[2];
    const float* features  = (const float*)d_in[3];
    float* out = (float*)d_out;

    hist_kernel<<<BQ / 256, 256>>>(coords, positions);
    scan_kernel<<<1, 1024>>>();
    scat_kernel<<<BQ / 256, 256>>>(coords, positions, weights);
    knn_grid_kernel<<<BQ / TPB, TPB>>>(features, out);
}